// round 11
// baseline (speedup 1.0000x reference)
#include <cuda_runtime.h>
#include <cuda_bf16.h>
#include <cstdint>

#define NROWS 65536
#define ZD    256
#define KCODES 1024
#define BM 128
#define NBLK (NROWS / BM)    // 512
#define MARGIN 8e-3f

#define ZQ_ELEMS ((size_t)NROWS * ZD)
#define IDX_OFF  ZQ_ELEMS
#define LOSS_OFF (ZQ_ELEMS + (size_t)NROWS)

#define LDTE 264                 // padded smem row (bf16 elements); 528 B stride
#define ROWB (LDTE * 2)          // 528
#define TILE_SM (BM * ROWB)      // 67584 B per tile
#define SZ_OFF 0
#define SE_OFF(b) (TILE_SM + (b) * TILE_SM)
#define DYN_SMEM (3 * TILE_SM)   // 202752 B

typedef unsigned long long ull;

__device__ float g_enorm[KCODES];
__device__ float g_znorm[NROWS];
__device__ float g_partial[NBLK];
__device__ __nv_bfloat16 g_Ebf16[(size_t)KCODES * ZD];   // 512 KB, row-major

// ---------------- PTX helpers ----------------
__device__ __forceinline__ uint32_t smem_u32(const void* p) {
    uint32_t a;
    asm("{ .reg .u64 t; cvta.to.shared.u64 t, %1; cvt.u32.u64 %0, t; }" : "=r"(a) : "l"(p));
    return a;
}
__device__ __forceinline__ void cp_async16(uint32_t dst, const void* src) {
    asm volatile("cp.async.cg.shared.global [%0], [%1], 16;" :: "r"(dst), "l"(src) : "memory");
}
#define CP_COMMIT() asm volatile("cp.async.commit_group;" ::: "memory")
#define CP_WAIT(N)  asm volatile("cp.async.wait_group %0;" :: "n"(N) : "memory")

__device__ __forceinline__ void ldsm_x4(uint32_t& r0, uint32_t& r1, uint32_t& r2, uint32_t& r3,
                                        uint32_t addr) {
    asm volatile("ldmatrix.sync.aligned.m8n8.x4.shared.b16 {%0,%1,%2,%3}, [%4];"
                 : "=r"(r0), "=r"(r1), "=r"(r2), "=r"(r3) : "r"(addr));
}
__device__ __forceinline__ void ldsm_x2(uint32_t& r0, uint32_t& r1, uint32_t addr) {
    asm volatile("ldmatrix.sync.aligned.m8n8.x2.shared.b16 {%0,%1}, [%2];"
                 : "=r"(r0), "=r"(r1) : "r"(addr));
}

// ================= K1: sum-of-squares per row, XLA row-reduce-tree bit-exact ==========
__global__ void sqsum_tree_kernel(const float* __restrict__ src, int nrows, int mode)
{
    int row = blockIdx.x * 8 + (threadIdx.x >> 5);
    if (row >= nrows) return;
    int lane = threadIdx.x & 31;
    const float2* p = (const float2*)(src + (size_t)row * ZD);
    float acc[4];
#pragma unroll
    for (int j = 0; j < 4; j++) {
        float2 v = p[lane + 32 * j];
        acc[j] = __fadd_rn(__fmul_rn(v.x, v.x), __fmul_rn(v.y, v.y));
    }
#pragma unroll
    for (int off = 16; off; off >>= 1)
#pragma unroll
        for (int j = 0; j < 4; j++)
            acc[j] = __fadd_rn(acc[j], __shfl_down_sync(0xffffffffu, acc[j], off));
    if (lane == 0) {
        float s = __fadd_rn(__fadd_rn(acc[0], acc[2]), __fadd_rn(acc[1], acc[3]));
        if (mode == 0) g_znorm[row] = s;
        else           g_enorm[row] = s;
    }
}

// ================= K1b: one-time E fp32 -> bf16 global conversion =================
__global__ void ecvt_kernel(const float* __restrict__ E)
{
    int idx = (blockIdx.x * 256 + threadIdx.x) * 4;   // 256 blocks x 256 thr x 4 elem
    float4 v = *(const float4*)(E + idx);
    __nv_bfloat162 b0 = __floats2bfloat162_rn(v.x, v.y);
    __nv_bfloat162 b1 = __floats2bfloat162_rn(v.z, v.w);
    uint2 pk;
    pk.x = *reinterpret_cast<unsigned*>(&b0);
    pk.y = *reinterpret_cast<unsigned*>(&b1);
    *(uint2*)(&g_Ebf16[idx]) = pk;
}

// ================= K2: HMMA candidate search (fused) + exact fp32 rescore =============
__global__ __launch_bounds__(256, 1) void vq_mma(
    const float* __restrict__ Z, const float* __restrict__ E, float* __restrict__ out)
{
    extern __shared__ __align__(16) char dyn[];
    __shared__ float sEn[KCODES];
    __shared__ unsigned sCand[8][512];
    __shared__ int sCnt[8];
    __shared__ ull sBest[BM];
    __shared__ float sRed[8];

    const int tid = threadIdx.x;
    const int wid = tid >> 5, lane = tid & 31;
    const int g = lane >> 2, t = lane & 3;       // quad coords
    const int row0 = blockIdx.x * BM;
    const int wr = wid * 16;                     // warp's 16-row slice

    const uint32_t smBase = smem_u32(dyn);
    const uint32_t smZ = smBase + SZ_OFF;

    for (int i = tid; i < KCODES; i += 256) sEn[i] = g_enorm[i];
    if (tid < BM) sBest[tid] = ~0ull;
    if (tid < 8)  sCnt[tid] = 0;

    // ---- Z tile: fp32 -> bf16 padded rows ----
#pragma unroll
    for (int it = 0; it < 16; it++) {
        int lin = (tid + it * 256) * 8;
        int r = lin >> 8, k = lin & 255;
        float4 v0 = *(const float4*)(Z + (size_t)(row0 + r) * ZD + k);
        float4 v1 = *(const float4*)(Z + (size_t)(row0 + r) * ZD + k + 4);
        __nv_bfloat162 b0 = __floats2bfloat162_rn(v0.x, v0.y);
        __nv_bfloat162 b1 = __floats2bfloat162_rn(v0.z, v0.w);
        __nv_bfloat162 b2 = __floats2bfloat162_rn(v1.x, v1.y);
        __nv_bfloat162 b3 = __floats2bfloat162_rn(v1.z, v1.w);
        uint4 pk;
        pk.x = *reinterpret_cast<unsigned*>(&b0);
        pk.y = *reinterpret_cast<unsigned*>(&b1);
        pk.z = *reinterpret_cast<unsigned*>(&b2);
        pk.w = *reinterpret_cast<unsigned*>(&b3);
        *(uint4*)(dyn + SZ_OFF + r * ROWB + k * 2) = pk;
    }

    // ---- cp.async E tile 0 into buffer 0 ----
#pragma unroll
    for (int i = 0; i < 16; i++) {
        int ch = tid + i * 256;                  // 4096 16B chunks per tile
        int r = ch >> 5, c16 = ch & 31;
        cp_async16(smBase + SE_OFF(0) + r * ROWB + c16 * 16,
                   (const char*)g_Ebf16 + (size_t)r * 512 + c16 * 16);
    }
    CP_COMMIT();

    // ldmatrix per-lane addresses
    const int lr = lane & 7, ls = lane >> 3;     // ls: 0..3 (x4) / 0..1 (x2)
    const uint32_t aAddr0 = smZ + (wr + (ls & 1) * 8 + lr) * ROWB + (ls >> 1) * 16;
    const uint32_t bRow0  = (uint32_t)((lane < 16 ? lr : 0) * ROWB + (lane < 16 ? (ls & 1) : 0) * 16);

    float runA = 3.402823466e38f, runB = 3.402823466e38f;

    for (int ct = 0; ct < 8; ct++) {
        const int buf = ct & 1;
        // issue next tile's cp.async into other buffer, then wait for current
        if (ct < 7) {
#pragma unroll
            for (int i = 0; i < 16; i++) {
                int ch = tid + i * 256;
                int r = ch >> 5, c16 = ch & 31;
                cp_async16(smBase + SE_OFF(buf ^ 1) + r * ROWB + c16 * 16,
                           (const char*)g_Ebf16 + (size_t)(ct + 1) * 128 * 512
                                                + (size_t)r * 512 + c16 * 16);
            }
            CP_COMMIT();
            CP_WAIT(1);
        } else {
            CP_WAIT(0);
        }
        __syncthreads();    // tile ct resident for all; prev compute done (tail barrier)

        const uint32_t smE = smBase + SE_OFF(buf);
        float dacc[16][4];
#pragma unroll
        for (int nb = 0; nb < 16; nb++) {
            dacc[nb][0] = 0.f; dacc[nb][1] = 0.f; dacc[nb][2] = 0.f; dacc[nb][3] = 0.f;
        }
#pragma unroll
        for (int ks = 0; ks < 16; ks++) {
            uint32_t a0, a1, a2, a3;
            ldsm_x4(a0, a1, a2, a3, aAddr0 + ks * 32);
#pragma unroll
            for (int nb = 0; nb < 16; nb++) {
                uint32_t b0, b1;
                ldsm_x2(b0, b1, smE + bRow0 + nb * (8 * ROWB) + ks * 32);
                asm volatile(
                    "mma.sync.aligned.m16n8k16.row.col.f32.bf16.bf16.f32 "
                    "{%0,%1,%2,%3}, {%4,%5,%6,%7}, {%8,%9}, {%0,%1,%2,%3};"
                    : "+f"(dacc[nb][0]), "+f"(dacc[nb][1]),
                      "+f"(dacc[nb][2]), "+f"(dacc[nb][3])
                    : "r"(a0), "r"(a1), "r"(a2), "r"(a3), "r"(b0), "r"(b1));
            }
        }

        // ---- per-tile processing: row mins -> running limit -> candidate push ----
        float tA = 3.402823466e38f, tB = 3.402823466e38f;
        float v[16][4];
#pragma unroll
        for (int nb = 0; nb < 16; nb++) {
            int c0 = ct * 128 + nb * 8 + 2 * t;
            float e0 = sEn[c0], e1 = sEn[c0 + 1];
            v[nb][0] = __fmaf_rn(-2.0f, dacc[nb][0], e0);
            v[nb][1] = __fmaf_rn(-2.0f, dacc[nb][1], e1);
            v[nb][2] = __fmaf_rn(-2.0f, dacc[nb][2], e0);
            v[nb][3] = __fmaf_rn(-2.0f, dacc[nb][3], e1);
            tA = fminf(tA, fminf(v[nb][0], v[nb][1]));
            tB = fminf(tB, fminf(v[nb][2], v[nb][3]));
        }
        tA = fminf(tA, __shfl_xor_sync(0xffffffffu, tA, 1));
        tA = fminf(tA, __shfl_xor_sync(0xffffffffu, tA, 2));
        tB = fminf(tB, __shfl_xor_sync(0xffffffffu, tB, 1));
        tB = fminf(tB, __shfl_xor_sync(0xffffffffu, tB, 2));
        float limA = fminf(runA, tA) + MARGIN;
        float limB = fminf(runB, tB) + MARGIN;
        int rowA = wr + g, rowB = wr + g + 8;
#pragma unroll
        for (int nb = 0; nb < 16; nb++) {
            int c0 = ct * 128 + nb * 8 + 2 * t;
            if (v[nb][0] < limA) {
                int s = atomicAdd(&sCnt[wid], 1);
                if (s < 512) sCand[wid][s] = (unsigned)((rowA << 10) | c0);
            }
            if (v[nb][1] < limA) {
                int s = atomicAdd(&sCnt[wid], 1);
                if (s < 512) sCand[wid][s] = (unsigned)((rowA << 10) | (c0 + 1));
            }
            if (v[nb][2] < limB) {
                int s = atomicAdd(&sCnt[wid], 1);
                if (s < 512) sCand[wid][s] = (unsigned)((rowB << 10) | c0);
            }
            if (v[nb][3] < limB) {
                int s = atomicAdd(&sCnt[wid], 1);
                if (s < 512) sCand[wid][s] = (unsigned)((rowB << 10) | (c0 + 1));
            }
        }
        runA = limA - MARGIN;
        runB = limB - MARGIN;
        __syncthreads();    // compute done before next iter overwrites buf^1's sibling
    }

    // ================= exact fp32 rescore (reference op order) =================
    {
        int cnt = sCnt[wid];
        if (cnt > 512) cnt = 512;
        for (int base = 0; base < cnt; base += 32) {
            int idx = base + lane;
            if (idx < cnt) {
                unsigned e = sCand[wid][idx];
                int i = e >> 10;
                int c = e & 1023;
                int r = row0 + i;
                const float4* zp = (const float4*)(Z + (size_t)r * ZD);
                const float4* ep = (const float4*)(E + (size_t)c * ZD);
                float acc = 0.0f;     // serial k-ascending single-accumulator chain
#pragma unroll 8
                for (int k = 0; k < 64; k++) {
                    float4 a = zp[k];
                    float4 b = ep[k];
                    acc = __fmaf_rn(a.x, b.x, acc);
                    acc = __fmaf_rn(a.y, b.y, acc);
                    acc = __fmaf_rn(a.z, b.z, acc);
                    acc = __fmaf_rn(a.w, b.w, acc);
                }
                float s = __fmaf_rn(-2.0f, acc, __fadd_rn(g_znorm[r], sEn[c]));
                ull key = ((ull)__float_as_uint(s) << 32) | (unsigned)c;   // s > 0
                atomicMin(&sBest[i], key);   // min score, tie -> min index
            }
        }
    }
    __syncthreads();

    // ================= epilogue: gather z_q; z_q_st = fl(z + fl(z_q - z)); loss ========
    const float* Ablk = Z + (size_t)row0 * ZD;
    float lsum = 0.0f;
    for (int e2 = tid; e2 < BM * (ZD / 4); e2 += 256) {
        int m = e2 >> 6;
        int c4 = (e2 & 63) * 4;
        int idx = (int)(unsigned)(sBest[m] & 0xffffffffull);
        float4 q  = *(const float4*)(E + (size_t)idx * ZD + c4);
        float4 z4 = *(const float4*)(Ablk + (size_t)m * ZD + c4);
        float d0 = __fadd_rn(q.x, -z4.x), d1 = __fadd_rn(q.y, -z4.y);
        float d2 = __fadd_rn(q.z, -z4.z), d3 = __fadd_rn(q.w, -z4.w);
        float4 o;
        o.x = __fadd_rn(z4.x, d0); o.y = __fadd_rn(z4.y, d1);
        o.z = __fadd_rn(z4.z, d2); o.w = __fadd_rn(z4.w, d3);
        lsum += d0 * d0 + d1 * d1 + d2 * d2 + d3 * d3;
        *(float4*)(out + (size_t)(row0 + m) * ZD + c4) = o;
    }
    if (tid < BM) out[IDX_OFF + row0 + tid] = (float)(unsigned)(sBest[tid] & 0xffffffffull);

#pragma unroll
    for (int o = 16; o; o >>= 1) lsum += __shfl_xor_sync(0xffffffffu, lsum, o);
    if ((tid & 31) == 0) sRed[tid >> 5] = lsum;
    __syncthreads();
    if (tid < 8) {
        float x = sRed[tid];
        x += __shfl_xor_sync(0xffu, x, 4);
        x += __shfl_xor_sync(0xffu, x, 2);
        x += __shfl_xor_sync(0xffu, x, 1);
        if (tid == 0) g_partial[blockIdx.x] = x;
    }
}

// ================= K3: deterministic final loss reduction =================
__global__ void finalize_kernel(float* __restrict__ out) {
    __shared__ float s[16];
    int t = threadIdx.x;
    float v = g_partial[t];
#pragma unroll
    for (int o = 16; o; o >>= 1) v += __shfl_xor_sync(0xffffffffu, v, o);
    if ((t & 31) == 0) s[t >> 5] = v;
    __syncthreads();
    if (t < 16) {
        float x = s[t];
        x += __shfl_xor_sync(0xffffu, x, 8);
        x += __shfl_xor_sync(0xffffu, x, 4);
        x += __shfl_xor_sync(0xffffu, x, 2);
        x += __shfl_xor_sync(0xffffu, x, 1);
        if (t == 0) {
            float mean = x / (float)((size_t)NROWS * ZD);
            out[LOSS_OFF] = mean + 0.25f * mean;   // (1 + BETA) * mean((z_q - z)^2)
        }
    }
}

extern "C" void kernel_launch(void* const* d_in, const int* in_sizes, int n_in,
                              void* d_out, int out_size) {
    const float* Z = (const float*)d_in[0];
    const float* E = (const float*)d_in[1];
    if (n_in >= 2 && in_sizes[0] < in_sizes[1]) { const float* t = Z; Z = E; E = t; }
    float* out = (float*)d_out;

    cudaFuncSetAttribute(vq_mma, cudaFuncAttributeMaxDynamicSharedMemorySize, DYN_SMEM);

    sqsum_tree_kernel<<<(NROWS + 7) / 8, 256>>>(Z, NROWS, 0);   // -> g_znorm
    sqsum_tree_kernel<<<(KCODES + 7) / 8, 256>>>(E, KCODES, 1); // -> g_enorm
    ecvt_kernel<<<KCODES * ZD / 1024, 256>>>(E);                // -> g_Ebf16
    vq_mma<<<NBLK, 256, DYN_SMEM>>>(Z, E, out);
    finalize_kernel<<<1, 512>>>(out);
}